// round 10
// baseline (speedup 1.0000x reference)
#include <cuda_runtime.h>
#include <cuda_bf16.h>
#include <cstdint>
#include <math.h>

#define BB   2
#define SS   2048
#define HHID 2048
#define NHQ  16
#define NKVH 4
#define DDIM 128
#define TTOK (BB*SS)     // 4096
#define PAD_ROWS 4224    // 33 tiles of 128

// ---------------- static scratch (~85MB total; proven-safe range) ----------------
__device__ __align__(16) int g_src[PAD_ROWS];   // sorted row -> src token (-1 = pad)
__device__ __align__(16) int g_dst[TTOK];       // src token -> sorted row
__device__ unsigned g_tiles0_dev;
__device__ __align__(16) float g_q [(size_t)BB*NHQ *SS*DDIM];
__device__ __align__(16) float g_k [(size_t)BB*NKVH*SS*DDIM];
__device__ __align__(16) float g_v [(size_t)BB*NKVH*SS*DDIM];
__device__ __align__(16) __nv_bfloat16 g_Ao_hi[(size_t)PAD_ROWS*HHID];  // sorted rows
__device__ __align__(16) __nv_bfloat16 g_Ao_lo[(size_t)PAD_ROWS*HHID];

// ---------------- helpers ----------------
__device__ __forceinline__ void mma16816(float* d, const uint32_t* a, const uint32_t* b) {
    asm volatile("mma.sync.aligned.m16n8k16.row.col.f32.bf16.bf16.f32 "
        "{%0,%1,%2,%3}, {%4,%5,%6,%7}, {%8,%9}, {%0,%1,%2,%3};"
        : "+f"(d[0]), "+f"(d[1]), "+f"(d[2]), "+f"(d[3])
        : "r"(a[0]), "r"(a[1]), "r"(a[2]), "r"(a[3]), "r"(b[0]), "r"(b[1]));
}
__device__ __forceinline__ void split2(float x, float y, uint32_t& hi, uint32_t& lo) {
    __nv_bfloat16 hx = __float2bfloat16(x), hy = __float2bfloat16(y);
    float rx = x - __bfloat162float(hx), ry = y - __bfloat162float(hy);
    hi = (uint32_t)__bfloat16_as_ushort(hx) | ((uint32_t)__bfloat16_as_ushort(hy) << 16);
    lo = (uint32_t)__bfloat16_as_ushort(__float2bfloat16(rx))
       | ((uint32_t)__bfloat16_as_ushort(__float2bfloat16(ry)) << 16);
}

// smem word-layout constants for the tensor GEMM
#define SWW   21                  // 32-bit words per row (42 bf16, padded)
#define LIMBB (128*SWW*4)         // 10752 bytes per limb buffer
#define OA_H  0
#define OA_L  (LIMBB)
#define OB_H  (2*LIMBB)
#define OB_L  (3*LIMBB)
#define OWF   (4*LIMBB)           // fp32 staging [32][132] = 16896
#define SMEM_GEMM 67584           // max(conversion 59904, epilogue fs 128*132*4)

// ===================== kernel: expert scan / permutation =====================
__global__ __launch_bounds__(1024) void scan_kernel(const int* __restrict__ tt)
{
    __shared__ int wtot[32];
    int tid = threadIdx.x, lane = tid & 31, wid = tid >> 5;
    for (int j = tid; j < PAD_ROWS; j += 1024) g_src[j] = -1;
    __syncthreads();

    int t0 = tid * 4;
    int cs[4];
#pragma unroll
    for (int i = 0; i < 4; i++) cs[i] = tt[t0 + i];
    int loc = cs[0] + cs[1] + cs[2] + cs[3];
    int inc = loc;
#pragma unroll
    for (int o = 1; o < 32; o <<= 1) { int v = __shfl_up_sync(0xffffffffu, inc, o); if (lane >= o) inc += v; }
    if (lane == 31) wtot[wid] = inc;
    __syncthreads();
    if (wid == 0) {
        int v = wtot[lane];
#pragma unroll
        for (int o = 1; o < 32; o <<= 1) { int u = __shfl_up_sync(0xffffffffu, v, o); if (lane >= o) v += u; }
        wtot[lane] = v;
    }
    __syncthreads();
    int total1 = wtot[31];
    int base1  = (wid > 0 ? wtot[wid - 1] : 0) + (inc - loc);
    int n0 = TTOK - total1;
    int tiles0 = (n0 + 127) >> 7;
    if (tid == 0) g_tiles0_dev = (unsigned)tiles0;
    int off1 = tiles0 * 128;
    int run1 = base1;
#pragma unroll
    for (int i = 0; i < 4; i++) {
        int idx = t0 + i;
        int dst = cs[i] ? (off1 + run1) : (idx - run1);
        g_dst[idx] = dst;
        g_src[dst] = idx;
        run1 += cs[i];
    }
}

// ===================== kernel: zero pad rows of Ao (before oproj) =====================
__global__ __launch_bounds__(256) void zeropad_kernel()
{
    int row = blockIdx.x;
    if (g_src[row] >= 0) return;
    uint4 z = make_uint4(0u, 0u, 0u, 0u);
    size_t o = (size_t)row * 2048 + threadIdx.x * 8;
    *(uint4*)&g_Ao_hi[o] = z;
    *(uint4*)&g_Ao_lo[o] = z;
}

// ===================== tensor-core mainloop pieces =====================
// B tile: stage fp32 [32k][132] coalesced, then transpose-convert to [128n][42] bf16 hi/lo
__device__ __forceinline__ void stageB(float* sWf, const float* __restrict__ W,
                                       int nstr, int n0, int k0, int tid)
{
#pragma unroll
    for (int it = 0; it < 4; it++) {
        int f = tid + it * 256;
        int kr = f >> 5, nc = f & 31;
        *(float4*)&sWf[kr * 132 + nc * 4] = *(const float4*)&W[(size_t)(k0 + kr) * nstr + n0 + nc * 4];
    }
}
__device__ __forceinline__ void convB(const float* sWf, uint32_t* wBh, uint32_t* wBl, int tid)
{
    const int n = tid >> 1, kh = tid & 1;
    uint32_t hw[8], lw[8];
#pragma unroll
    for (int j = 0; j < 16; j += 2) {
        float x0 = sWf[(kh * 16 + j)     * 132 + n];
        float x1 = sWf[(kh * 16 + j + 1) * 132 + n];
        split2(x0, x1, hw[j >> 1], lw[j >> 1]);
    }
    int wo = n * SWW + kh * 8;
#pragma unroll
    for (int jj = 0; jj < 8; jj++) { wBh[wo + jj] = hw[jj]; wBl[wo + jj] = lw[jj]; }
}
// fragment loads + 3-limb mma for one 32-k chunk
__device__ __forceinline__ void mma_chunk(const char* sm, int wm, int wn, int g, int t,
                                          float acc[4][4][4])
{
    const uint32_t* wAh = (const uint32_t*)(sm + OA_H);
    const uint32_t* wAl = (const uint32_t*)(sm + OA_L);
    const uint32_t* wBh = (const uint32_t*)(sm + OB_H);
    const uint32_t* wBl = (const uint32_t*)(sm + OB_L);
#pragma unroll
    for (int ks = 0; ks < 2; ks++) {
        const int kb = ks * 8 + t;
        uint32_t ah[4][4], al[4][4], bh[4][2], bl[4][2];
#pragma unroll
        for (int mt = 0; mt < 4; mt++) {
            int ro = (wm * 64 + mt * 16 + g) * SWW + kb;
            ah[mt][0] = wAh[ro];     ah[mt][1] = wAh[ro + 8 * SWW];
            ah[mt][2] = wAh[ro + 4]; ah[mt][3] = wAh[ro + 8 * SWW + 4];
            al[mt][0] = wAl[ro];     al[mt][1] = wAl[ro + 8 * SWW];
            al[mt][2] = wAl[ro + 4]; al[mt][3] = wAl[ro + 8 * SWW + 4];
        }
#pragma unroll
        for (int nt = 0; nt < 4; nt++) {
            int no = (wn * 32 + nt * 8 + g) * SWW + kb;
            bh[nt][0] = wBh[no]; bh[nt][1] = wBh[no + 4];
            bl[nt][0] = wBl[no]; bl[nt][1] = wBl[no + 4];
        }
#pragma unroll
        for (int mt = 0; mt < 4; mt++)
#pragma unroll
            for (int nt = 0; nt < 4; nt++) {
                mma16816(acc[mt][nt], ah[mt], bh[nt]);
                mma16816(acc[mt][nt], ah[mt], bl[nt]);
                mma16816(acc[mt][nt], al[mt], bh[nt]);
            }
    }
}

// ===================== kernel: QKV projection (tensor 3-limb) + bias + RoPE =====================
// grid (33, 24): ct 0..15 Q, 16..19 K, 20..23 V. block 256.
__global__ __launch_bounds__(256) void qkv_mma_kernel(
    const float* __restrict__ hs,
    const float* __restrict__ Wq, const float* __restrict__ bq,
    const float* __restrict__ Wk, const float* __restrict__ bk,
    const float* __restrict__ Wv, const float* __restrict__ bv,
    const float* __restrict__ cosp, const float* __restrict__ sinp)
{
    extern __shared__ char smq[];
    const int tid = threadIdx.x, lane = tid & 31, wid = tid >> 5;
    const int g = lane >> 2, t = lane & 3;
    const int wm = wid & 1, wn = wid >> 1;
    const int r2 = tid >> 1, kh = tid & 1;

    const int rt = blockIdx.x, ct = blockIdx.y;
    const int tiles0 = (int)g_tiles0_dev;
    const int e = (rt < tiles0) ? 0 : 1;
    const int m0 = rt * 128;

    const float* W; const float* bias; int nstr, n0, which, head;
    if (ct < 16)      { W = Wq; bias = bq; nstr = 2048; n0 = ct * 128;        which = 0; head = ct;      }
    else if (ct < 20) { W = Wk; bias = bk; nstr = 512;  n0 = (ct - 16) * 128; which = 1; head = ct - 16; }
    else              { W = Wv; bias = bv; nstr = 512;  n0 = (ct - 20) * 128; which = 2; head = ct - 20; }
    W    += (size_t)e * 2048 * nstr;
    bias += (size_t)e * nstr;

    uint32_t* wAh = (uint32_t*)(smq + OA_H);
    uint32_t* wAl = (uint32_t*)(smq + OA_L);
    uint32_t* wBh = (uint32_t*)(smq + OB_H);
    uint32_t* wBl = (uint32_t*)(smq + OB_L);
    float* sWf = (float*)(smq + OWF);

    const int asrc = g_src[m0 + r2];

    float acc[4][4][4];
#pragma unroll
    for (int mt = 0; mt < 4; mt++)
#pragma unroll
        for (int nt = 0; nt < 4; nt++)
#pragma unroll
            for (int c = 0; c < 4; c++) acc[mt][nt][c] = 0.f;

    for (int k0 = 0; k0 < 2048; k0 += 32) {
        // A: gathered hs rows -> bf16 hi/lo words
#pragma unroll
        for (int j = 0; j < 4; j++) {
            float4 v = make_float4(0.f, 0.f, 0.f, 0.f);
            if (asrc >= 0) v = *(const float4*)&hs[(size_t)asrc * 2048 + k0 + kh * 16 + j * 4];
            uint32_t h0, l0, h1, l1;
            split2(v.x, v.y, h0, l0);
            split2(v.z, v.w, h1, l1);
            int wo = r2 * SWW + kh * 8 + j * 2;
            wAh[wo] = h0; wAh[wo + 1] = h1;
            wAl[wo] = l0; wAl[wo + 1] = l1;
        }
        stageB(sWf, W, nstr, n0, k0, tid);
        __syncthreads();
        convB(sWf, wBh, wBl, tid);
        __syncthreads();
        mma_chunk(smq, wm, wn, g, t, acc);
        __syncthreads();
    }

    // stage acc tile as fp32 [128][132]
    float* fs = (float*)smq;
#pragma unroll
    for (int mt = 0; mt < 4; mt++) {
        int row0 = wm * 64 + mt * 16 + g;
#pragma unroll
        for (int nt = 0; nt < 4; nt++) {
            int col0 = wn * 32 + nt * 8 + 2 * t;
            *(float2*)&fs[row0 * 132 + col0]       = make_float2(acc[mt][nt][0], acc[mt][nt][1]);
            *(float2*)&fs[(row0 + 8) * 132 + col0] = make_float2(acc[mt][nt][2], acc[mt][nt][3]);
        }
    }
    __syncthreads();

    // ---- row epilogue (Round-6 proven): bias + RoPE + scatter ----
    const int r = tid & 127, hf = tid >> 7;
    const int src = g_src[m0 + r];
    if (src >= 0) {
        const int b = src >> 11, s = src & 2047;
        const float* bp = bias + n0;
        const float* row = fs + r * 132;
        float* dstp;
        if (which == 0)      dstp = &g_q[((size_t)((b * NHQ  + head) * SS + s)) * DDIM];
        else if (which == 1) dstp = &g_k[((size_t)((b * NKVH + head) * SS + s)) * DDIM];
        else                 dstp = &g_v[((size_t)((b * NKVH + head) * SS + s)) * DDIM];
        if (which < 2) {
            const size_t cb = ((size_t)(b * 2048 + s)) * 128;
#pragma unroll 4
            for (int j0 = 0; j0 < 64; j0 += 4) {
                float o[4];
#pragma unroll
                for (int jj = 0; jj < 4; jj++) {
                    int j = j0 + jj;
                    float x0 = row[j]      + __ldg(&bp[j]);
                    float x1 = row[j + 64] + __ldg(&bp[j + 64]);
                    if (hf == 0)
                        o[jj] = x0 * __ldg(&cosp[cb + j])      - x1 * __ldg(&sinp[cb + j]);
                    else
                        o[jj] = x1 * __ldg(&cosp[cb + 64 + j]) + x0 * __ldg(&sinp[cb + 64 + j]);
                }
                *(float4*)&dstp[hf * 64 + j0] = make_float4(o[0], o[1], o[2], o[3]);
            }
        } else {
#pragma unroll 4
            for (int j0 = 0; j0 < 64; j0 += 4) {
                float o[4];
#pragma unroll
                for (int jj = 0; jj < 4; jj++) {
                    int d = hf * 64 + j0 + jj;
                    o[jj] = row[d] + __ldg(&bp[d]);
                }
                *(float4*)&dstp[hf * 64 + j0] = make_float4(o[0], o[1], o[2], o[3]);
            }
        }
    }
}

// ===================== kernel: O projection (tensor 3-limb, A preconverted) =====================
// grid (33, 16). block 256.
__global__ __launch_bounds__(256) void oproj_mma_kernel(
    const float* __restrict__ Wo, float* __restrict__ out)
{
    extern __shared__ char smo[];
    const int tid = threadIdx.x, lane = tid & 31, wid = tid >> 5;
    const int g = lane >> 2, t = lane & 3;
    const int wm = wid & 1, wn = wid >> 1;
    const int r2 = tid >> 1, kh = tid & 1;

    const int rt = blockIdx.x, ct = blockIdx.y;
    const int tiles0 = (int)g_tiles0_dev;
    const int e = (rt < tiles0) ? 0 : 1;
    const int m0 = rt * 128, n0 = ct * 128;
    const float* W = Wo + (size_t)e * 2048 * 2048;

    uint32_t* wAh = (uint32_t*)(smo + OA_H);
    uint32_t* wAl = (uint32_t*)(smo + OA_L);
    uint32_t* wBh = (uint32_t*)(smo + OB_H);
    uint32_t* wBl = (uint32_t*)(smo + OB_L);
    float* sWf = (float*)(smo + OWF);

    const size_t arow = (size_t)(m0 + r2) * 2048;

    float acc[4][4][4];
#pragma unroll
    for (int mt = 0; mt < 4; mt++)
#pragma unroll
        for (int nt = 0; nt < 4; nt++)
#pragma unroll
            for (int c = 0; c < 4; c++) acc[mt][nt][c] = 0.f;

    for (int k0 = 0; k0 < 2048; k0 += 32) {
        // A: direct bf16 hi/lo loads (sorted rows, pads zeroed)
        {
            uint4 hv0 = *(const uint4*)&g_Ao_hi[arow + k0 + kh * 16];
            uint4 hv1 = *(const uint4*)&g_Ao_hi[arow + k0 + kh * 16 + 8];
            uint4 lv0 = *(const uint4*)&g_Ao_lo[arow + k0 + kh * 16];
            uint4 lv1 = *(const uint4*)&g_Ao_lo[arow + k0 + kh * 16 + 8];
            int wo = r2 * SWW + kh * 8;
            wAh[wo + 0] = hv0.x; wAh[wo + 1] = hv0.y; wAh[wo + 2] = hv0.z; wAh[wo + 3] = hv0.w;
            wAh[wo + 4] = hv1.x; wAh[wo + 5] = hv1.y; wAh[wo + 6] = hv1.z; wAh[wo + 7] = hv1.w;
            wAl[wo + 0] = lv0.x; wAl[wo + 1] = lv0.y; wAl[wo + 2] = lv0.z; wAl[wo + 3] = lv0.w;
            wAl[wo + 4] = lv1.x; wAl[wo + 5] = lv1.y; wAl[wo + 6] = lv1.z; wAl[wo + 7] = lv1.w;
        }
        stageB(sWf, W, 2048, n0, k0, tid);
        __syncthreads();
        convB(sWf, wBh, wBl, tid);
        __syncthreads();
        mma_chunk(smo, wm, wn, g, t, acc);
        __syncthreads();
    }

    // epilogue: fragment-direct scatter to token order
#pragma unroll
    for (int mt = 0; mt < 4; mt++) {
        int row0 = m0 + wm * 64 + mt * 16 + g;
        int s0 = g_src[row0], s1 = g_src[row0 + 8];
#pragma unroll
        for (int nt = 0; nt < 4; nt++) {
            int col = n0 + wn * 32 + nt * 8 + 2 * t;
            if (s0 >= 0) *(float2*)&out[(size_t)s0 * 2048 + col] = make_float2(acc[mt][nt][0], acc[mt][nt][1]);
            if (s1 >= 0) *(float2*)&out[(size_t)s1 * 2048 + col] = make_float2(acc[mt][nt][2], acc[mt][nt][3]);
        }
    }
}

// ===================== kernel: causal flash attention (fp32 SIMT, bf16-split epilogue) =====================
__global__ __launch_bounds__(256) void attn_kernel()
{
    extern __shared__ float sm[];
    float* sQt = sm;               // [128 d][128 r]
    float* sKt = sm + 16384;       // [128 d][64 c]
    float* sV  = sm + 24576;       // [64 c][128 d]
    float* sPt = sm + 32768;       // [64 c][128 r]

    const int bh = blockIdx.y;
    const int b = bh >> 4, h = bh & 15, hk = h >> 2;
    const int qt = 15 - blockIdx.x;
    const int q0 = qt * 128;
    const float* Q = g_q + (size_t)(b * NHQ  + h ) * SS * DDIM;
    const float* K = g_k + (size_t)(b * NKVH + hk) * SS * DDIM;
    const float* V = g_v + (size_t)(b * NKVH + hk) * SS * DDIM;

    const int tid = threadIdx.x;
    const int tx = tid & 15, ty = tid >> 4;

#pragma unroll
    for (int it = 0; it < 16; it++) {
        int f = tid + it * 256;
        int r = f >> 5, dc = f & 31;
        float4 v = *(const float4*)&Q[(size_t)(q0 + r) * DDIM + dc * 4];
        sQt[(dc * 4 + 0) * 128 + r] = v.x;
        sQt[(dc * 4 + 1) * 128 + r] = v.y;
        sQt[(dc * 4 + 2) * 128 + r] = v.z;
        sQt[(dc * 4 + 3) * 128 + r] = v.w;
    }

    float accO[8][8];
    float mrow[8], lrow[8];
#pragma unroll
    for (int i = 0; i < 8; i++) {
        mrow[i] = -1e30f; lrow[i] = 0.f;
#pragma unroll
        for (int j = 0; j < 8; j++) accO[i][j] = 0.f;
    }

    const float scale = 0.08838834764831845f;
    const int ktiles = 2 * qt + 2;

    for (int kt = 0; kt < ktiles; kt++) {
        const int k0 = kt * 64;
        __syncthreads();
#pragma unroll
        for (int it = 0; it < 8; it++) {
            int f = tid + it * 256;
            int c = f >> 5, dc = f & 31;
            float4 v = *(const float4*)&K[(size_t)(k0 + c) * DDIM + dc * 4];
            sKt[(dc * 4 + 0) * 64 + c] = v.x;
            sKt[(dc * 4 + 1) * 64 + c] = v.y;
            sKt[(dc * 4 + 2) * 64 + c] = v.z;
            sKt[(dc * 4 + 3) * 64 + c] = v.w;
        }
#pragma unroll
        for (int it = 0; it < 8; it++) {
            int f = tid + it * 256;
            int c = f >> 5, dc = f & 31;
            *(float4*)&sV[c * 128 + dc * 4] = *(const float4*)&V[(size_t)(k0 + c) * DDIM + dc * 4];
        }
        __syncthreads();

        float sc[8][4];
#pragma unroll
        for (int i = 0; i < 8; i++)
#pragma unroll
            for (int j = 0; j < 4; j++) sc[i][j] = 0.f;
#pragma unroll 8
        for (int d = 0; d < 128; d++) {
            float qf[8], kf[4];
            *(float4*)&qf[0] = *(float4*)&sQt[d * 128 + ty * 8];
            *(float4*)&qf[4] = *(float4*)&sQt[d * 128 + ty * 8 + 4];
            *(float4*)&kf[0] = *(float4*)&sKt[d * 64 + tx * 4];
#pragma unroll
            for (int i = 0; i < 8; i++)
#pragma unroll
                for (int j = 0; j < 4; j++)
                    sc[i][j] = fmaf(qf[i], kf[j], sc[i][j]);
        }
#pragma unroll
        for (int i = 0; i < 8; i++)
#pragma unroll
            for (int j = 0; j < 4; j++) sc[i][j] *= scale;
        if (k0 + 63 > q0) {
#pragma unroll
            for (int i = 0; i < 8; i++)
#pragma unroll
                for (int j = 0; j < 4; j++)
                    if (k0 + tx * 4 + j > q0 + ty * 8 + i) sc[i][j] = -1e30f;
        }
#pragma unroll
        for (int i = 0; i < 8; i++) {
            float mx = fmaxf(fmaxf(sc[i][0], sc[i][1]), fmaxf(sc[i][2], sc[i][3]));
#pragma unroll
            for (int o = 1; o < 16; o <<= 1) mx = fmaxf(mx, __shfl_xor_sync(0xffffffffu, mx, o));
            float mn = fmaxf(mrow[i], mx);
            float alpha = __expf(mrow[i] - mn);
            mrow[i] = mn;
            float rs = 0.f;
#pragma unroll
            for (int j = 0; j < 4; j++) { float p = __expf(sc[i][j] - mn); sc[i][j] = p; rs += p; }
#pragma unroll
            for (int o = 1; o < 16; o <<= 1) rs += __shfl_xor_sync(0xffffffffu, rs, o);
            lrow[i] = lrow[i] * alpha + rs;
#pragma unroll
            for (int j = 0; j < 8; j++) accO[i][j] *= alpha;
        }
#pragma unroll
        for (int i = 0; i < 8; i++)
#pragma unroll
            for (int j = 0; j < 4; j++)
                sPt[(tx * 4 + j) * 128 + ty * 8 + i] = sc[i][j];
        __syncthreads();
#pragma unroll 4
        for (int c = 0; c < 64; c++) {
            float pf[8], vf[8];
            *(float4*)&pf[0] = *(float4*)&sPt[c * 128 + ty * 8];
            *(float4*)&pf[4] = *(float4*)&sPt[c * 128 + ty * 8 + 4];
            *(float4*)&vf[0] = *(float4*)&sV[c * 128 + tx * 8];
            *(float4*)&vf[4] = *(float4*)&sV[c * 128 + tx * 8 + 4];
#pragma unroll
            for (int i = 0; i < 8; i++)
#pragma unroll
                for (int j = 0; j < 8; j++)
                    accO[i][j] = fmaf(pf[i], vf[j], accO[i][j]);
        }
    }

    // ---- epilogue: normalize, split bf16 hi/lo, write SORTED rows ----
#pragma unroll
    for (int i = 0; i < 8; i++) {
        float inv = 1.f / lrow[i];
        int srow = q0 + ty * 8 + i;
        int dstrow = g_dst[b * 2048 + srow];
        __align__(16) unsigned short hh[8], ll[8];
#pragma unroll
        for (int j = 0; j < 8; j++) {
            float x = accO[i][j] * inv;
            __nv_bfloat16 hb = __float2bfloat16(x);
            hh[j] = __bfloat16_as_ushort(hb);
            ll[j] = __bfloat16_as_ushort(__float2bfloat16(x - __bfloat162float(hb)));
        }
        size_t o = (size_t)dstrow * 2048 + h * DDIM + tx * 8;
        *(uint4*)&g_Ao_hi[o] = *(uint4*)hh;
        *(uint4*)&g_Ao_lo[o] = *(uint4*)ll;
    }
}

// =====================================================================
extern "C" void kernel_launch(void* const* d_in, const int* in_sizes, int n_in,
                              void* d_out, int out_size)
{
    const float* hs   = (const float*)d_in[0];
    const int*   tt   = (const int*)  d_in[1];
    const float* cosp = (const float*)d_in[2];
    const float* sinp = (const float*)d_in[3];
    const float* Wq   = (const float*)d_in[4];
    const float* bq   = (const float*)d_in[5];
    const float* Wk   = (const float*)d_in[6];
    const float* bk   = (const float*)d_in[7];
    const float* Wv   = (const float*)d_in[8];
    const float* bv   = (const float*)d_in[9];
    const float* Wo   = (const float*)d_in[10];
    float* out = (float*)d_out;

    cudaFuncSetAttribute(attn_kernel,      cudaFuncAttributeMaxDynamicSharedMemorySize, 163840);
    cudaFuncSetAttribute(qkv_mma_kernel,   cudaFuncAttributeMaxDynamicSharedMemorySize, SMEM_GEMM);
    cudaFuncSetAttribute(oproj_mma_kernel, cudaFuncAttributeMaxDynamicSharedMemorySize, SMEM_GEMM);

    scan_kernel<<<1, 1024>>>(tt);
    zeropad_kernel<<<PAD_ROWS, 256>>>();
    qkv_mma_kernel<<<dim3(33, 24), 256, SMEM_GEMM>>>(hs, Wq, bq, Wk, bk, Wv, bv, cosp, sinp);
    attn_kernel<<<dim3(16, 32), 256, 163840>>>();
    oproj_mma_kernel<<<dim3(33, 16), 256, SMEM_GEMM>>>(Wo, out);
}

// round 12
// speedup vs baseline: 1.3048x; 1.3048x over previous
#include <cuda_runtime.h>
#include <cstdint>
#include <math.h>

#define BB   2
#define SS   2048
#define HHID 2048
#define NHQ  16
#define NKVH 4
#define DDIM 128
#define TTOK (BB*SS)     // 4096
#define PAD_ROWS 4224    // 33 tiles of 128

// ---------------- scratch (~58MB, proven-safe) ----------------
__device__ __align__(16) int g_src[PAD_ROWS];   // sorted row -> src token (-1 = pad)
__device__ unsigned g_tiles0_dev;
__device__ __align__(16) float g_q [(size_t)BB*NHQ *SS*DDIM];   // [B][NH][S][D]  (post-RoPE)
__device__ __align__(16) float g_k [(size_t)BB*NKVH*SS*DDIM];   // [B][NKV][S][D] (post-RoPE)
__device__ __align__(16) float g_v [(size_t)BB*NKVH*SS*DDIM];
__device__ __align__(16) float g_ao[(size_t)TTOK*HHID];         // [B][S][NH*D] token order

// ===================== kernel: expert scan / permutation (unchanged, proven) =====================
__global__ __launch_bounds__(1024) void scan_kernel(const int* __restrict__ tt)
{
    __shared__ int wtot[32];
    int tid = threadIdx.x, lane = tid & 31, wid = tid >> 5;
    for (int j = tid; j < PAD_ROWS; j += 1024) g_src[j] = -1;
    __syncthreads();

    int t0 = tid * 4;
    int cs[4];
#pragma unroll
    for (int i = 0; i < 4; i++) cs[i] = tt[t0 + i];
    int loc = cs[0] + cs[1] + cs[2] + cs[3];
    int inc = loc;
#pragma unroll
    for (int o = 1; o < 32; o <<= 1) { int v = __shfl_up_sync(0xffffffffu, inc, o); if (lane >= o) inc += v; }
    if (lane == 31) wtot[wid] = inc;
    __syncthreads();
    if (wid == 0) {
        int v = wtot[lane];
#pragma unroll
        for (int o = 1; o < 32; o <<= 1) { int u = __shfl_up_sync(0xffffffffu, v, o); if (lane >= o) v += u; }
        wtot[lane] = v;
    }
    __syncthreads();
    int total1 = wtot[31];
    int base1  = (wid > 0 ? wtot[wid - 1] : 0) + (inc - loc);
    int n0 = TTOK - total1;
    int tiles0 = (n0 + 127) >> 7;
    if (tid == 0) g_tiles0_dev = (unsigned)tiles0;
    int off1 = tiles0 * 128;
    int run1 = base1;
#pragma unroll
    for (int i = 0; i < 4; i++) {
        int idx = t0 + i;
        int dst = cs[i] ? (off1 + run1) : (idx - run1);
        g_src[dst] = idx;
        run1 += cs[i];
    }
}

// ===================== GEMM mainloop (k-tile 32, register-prefetch double buffer) =====================
// As: [32 k][132 pad] transposed A; Bs: [32 k][128 n].
// A loader: thread owns rows (tid>>2, tid>>2+64), granules (tid&3, (tid&3)+4).
// B loader: 4 x (f=tid+it*256 -> kr=f>>5, nc=f&31).
struct GemmRegs {
    float4 a[2][2];   // [rowhalf][granule half]
    float4 b[4];
};

__device__ __forceinline__ void gemm_load_regs(GemmRegs& R,
    const float* __restrict__ A, int asrc0, int asrc1, int ag,
    const float* __restrict__ W, int nstr, int n0, int k0, int tid)
{
    const float4 z = make_float4(0.f, 0.f, 0.f, 0.f);
    R.a[0][0] = (asrc0 >= 0) ? *(const float4*)&A[(size_t)asrc0 * 2048 + k0 + ag * 4]       : z;
    R.a[0][1] = (asrc0 >= 0) ? *(const float4*)&A[(size_t)asrc0 * 2048 + k0 + (ag + 4) * 4] : z;
    R.a[1][0] = (asrc1 >= 0) ? *(const float4*)&A[(size_t)asrc1 * 2048 + k0 + ag * 4]       : z;
    R.a[1][1] = (asrc1 >= 0) ? *(const float4*)&A[(size_t)asrc1 * 2048 + k0 + (ag + 4) * 4] : z;
#pragma unroll
    for (int it = 0; it < 4; it++) {
        int f = tid + it * 256;
        int kr = f >> 5, nc = f & 31;
        R.b[it] = *(const float4*)&W[(size_t)(k0 + kr) * nstr + n0 + nc * 4];
    }
}

__device__ __forceinline__ void gemm_store_regs(const GemmRegs& R,
    float (*As)[132], float (*Bs)[128], int arow, int ag, int tid)
{
#pragma unroll
    for (int h = 0; h < 2; h++) {
        int g = ag + h * 4;
        As[g * 4 + 0][arow]      = R.a[0][h].x; As[g * 4 + 1][arow]      = R.a[0][h].y;
        As[g * 4 + 2][arow]      = R.a[0][h].z; As[g * 4 + 3][arow]      = R.a[0][h].w;
        As[g * 4 + 0][arow + 64] = R.a[1][h].x; As[g * 4 + 1][arow + 64] = R.a[1][h].y;
        As[g * 4 + 2][arow + 64] = R.a[1][h].z; As[g * 4 + 3][arow + 64] = R.a[1][h].w;
    }
#pragma unroll
    for (int it = 0; it < 4; it++) {
        int f = tid + it * 256;
        int kr = f >> 5, nc = f & 31;
        *(float4*)&Bs[kr][nc * 4] = R.b[it];
    }
}

__device__ __forceinline__ void gemm_compute(
    const float (*As)[132], const float (*Bs)[128], int tx, int ty, float acc[8][8])
{
#pragma unroll 8
    for (int kk = 0; kk < 32; kk++) {
        float a[8], b[8];
        *(float4*)&a[0] = *(float4*)&As[kk][ty * 8];
        *(float4*)&a[4] = *(float4*)&As[kk][ty * 8 + 4];
        *(float4*)&b[0] = *(float4*)&Bs[kk][tx * 8];
        *(float4*)&b[4] = *(float4*)&Bs[kk][tx * 8 + 4];
#pragma unroll
        for (int i = 0; i < 8; i++)
#pragma unroll
            for (int j = 0; j < 8; j++)
                acc[i][j] = fmaf(a[i], b[j], acc[i][j]);
    }
}

// ===================== kernel: QKV projection (fp32 SIMT, sorted experts) + bias + RoPE =====================
// grid (33, 24): ct 0..15 Q-heads, 16..19 K-heads, 20..23 V-heads. block 256.
__global__ __launch_bounds__(256) void qkv_kernel(
    const float* __restrict__ hs,
    const float* __restrict__ Wq, const float* __restrict__ bq,
    const float* __restrict__ Wk, const float* __restrict__ bk,
    const float* __restrict__ Wv, const float* __restrict__ bv,
    const float* __restrict__ cosp, const float* __restrict__ sinp)
{
    const int rt = blockIdx.x, ct = blockIdx.y;
    const int tiles0 = (int)g_tiles0_dev;
    const int e = (rt < tiles0) ? 0 : 1;
    const int m0 = rt * 128;

    const float* W; const float* bias; int nstr, n0, which, head;
    if (ct < 16)      { W = Wq; bias = bq; nstr = 2048; n0 = ct * 128;        which = 0; head = ct;      }
    else if (ct < 20) { W = Wk; bias = bk; nstr = 512;  n0 = (ct - 16) * 128; which = 1; head = ct - 16; }
    else              { W = Wv; bias = bv; nstr = 512;  n0 = (ct - 20) * 128; which = 2; head = ct - 20; }
    W    += (size_t)e * 2048 * nstr;
    bias += (size_t)e * nstr;

    __shared__ float As[32][132];
    __shared__ float Bs[32][128];

    const int tid = threadIdx.x;
    const int tx = tid & 15, ty = tid >> 4;
    const int arow = tid >> 2, ag = tid & 3;
    const int asrc0 = g_src[m0 + arow];
    const int asrc1 = g_src[m0 + arow + 64];

    float acc[8][8];
#pragma unroll
    for (int i = 0; i < 8; i++)
#pragma unroll
        for (int j = 0; j < 8; j++) acc[i][j] = 0.f;

    GemmRegs R;
    gemm_load_regs(R, hs, asrc0, asrc1, ag, W, nstr, n0, 0, tid);

    for (int k0 = 0; k0 < 2048; k0 += 32) {
        gemm_store_regs(R, As, Bs, arow, ag, tid);
        __syncthreads();
        if (k0 + 32 < 2048)
            gemm_load_regs(R, hs, asrc0, asrc1, ag, W, nstr, n0, k0 + 32, tid);
        gemm_compute(As, Bs, tx, ty, acc);
        __syncthreads();
    }

    // ---- epilogue: bias + fused RoPE (shfl pair) + scatter (R6 verbatim) ----
    const float* bp = bias + n0;
#pragma unroll
    for (int i = 0; i < 8; i++) {
        const int row = m0 + ty * 8 + i;
        const int src = g_src[row];
        const int sEff = (src >= 0) ? src : 0;
        const int b = sEff >> 11, s = sEff & 2047;

        float v8[8];
#pragma unroll
        for (int j = 0; j < 8; j++) v8[j] = acc[i][j] + __ldg(&bp[tx * 8 + j]);

        if (which < 2) {
            float p8[8];
#pragma unroll
            for (int j = 0; j < 8; j++) p8[j] = __shfl_xor_sync(0xffffffffu, v8[j], 8);
            const size_t cb = ((size_t)(b * 2048 + s)) * 128;
#pragma unroll
            for (int j = 0; j < 8; j++) {
                int col = tx * 8 + j;
                float c  = __ldg(&cosp[cb + col]);
                float sn = __ldg(&sinp[cb + col]);
                v8[j] = (tx < 8) ? (v8[j] * c - p8[j] * sn)
                                 : (v8[j] * c + p8[j] * sn);
            }
        }

        if (src >= 0) {
            float* dst;
            if (which == 0)      dst = &g_q[((size_t)((b * NHQ  + head) * SS + s)) * DDIM + tx * 8];
            else if (which == 1) dst = &g_k[((size_t)((b * NKVH + head) * SS + s)) * DDIM + tx * 8];
            else                 dst = &g_v[((size_t)((b * NKVH + head) * SS + s)) * DDIM + tx * 8];
            *(float4*)&dst[0] = make_float4(v8[0], v8[1], v8[2], v8[3]);
            *(float4*)&dst[4] = make_float4(v8[4], v8[5], v8[6], v8[7]);
        }
    }
}

// ===================== kernel: causal flash attention (fp32 SIMT) — R6 byte-identical =====================
__global__ __launch_bounds__(256) void attn_kernel()
{
    extern __shared__ float sm[];
    float* sQt = sm;               // [128 d][128 r]
    float* sKt = sm + 16384;       // [128 d][64 c]
    float* sV  = sm + 24576;       // [64 c][128 d]
    float* sPt = sm + 32768;       // [64 c][128 r]

    const int bh = blockIdx.y;
    const int b = bh >> 4, h = bh & 15, hk = h >> 2;
    const int qt = 15 - blockIdx.x;
    const int q0 = qt * 128;
    const float* Q = g_q + (size_t)(b * NHQ  + h ) * SS * DDIM;
    const float* K = g_k + (size_t)(b * NKVH + hk) * SS * DDIM;
    const float* V = g_v + (size_t)(b * NKVH + hk) * SS * DDIM;

    const int tid = threadIdx.x;
    const int tx = tid & 15, ty = tid >> 4;

#pragma unroll
    for (int it = 0; it < 16; it++) {
        int f = tid + it * 256;
        int r = f >> 5, dc = f & 31;
        float4 v = *(const float4*)&Q[(size_t)(q0 + r) * DDIM + dc * 4];
        sQt[(dc * 4 + 0) * 128 + r] = v.x;
        sQt[(dc * 4 + 1) * 128 + r] = v.y;
        sQt[(dc * 4 + 2) * 128 + r] = v.z;
        sQt[(dc * 4 + 3) * 128 + r] = v.w;
    }

    float accO[8][8];
    float mrow[8], lrow[8];
#pragma unroll
    for (int i = 0; i < 8; i++) {
        mrow[i] = -1e30f; lrow[i] = 0.f;
#pragma unroll
        for (int j = 0; j < 8; j++) accO[i][j] = 0.f;
    }

    const float scale = 0.08838834764831845f;
    const int ktiles = 2 * qt + 2;

    for (int kt = 0; kt < ktiles; kt++) {
        const int k0 = kt * 64;
        __syncthreads();
#pragma unroll
        for (int it = 0; it < 8; it++) {
            int f = tid + it * 256;
            int c = f >> 5, dc = f & 31;
            float4 v = *(const float4*)&K[(size_t)(k0 + c) * DDIM + dc * 4];
            sKt[(dc * 4 + 0) * 64 + c] = v.x;
            sKt[(dc * 4 + 1) * 64 + c] = v.y;
            sKt[(dc * 4 + 2) * 64 + c] = v.z;
            sKt[(dc * 4 + 3) * 64 + c] = v.w;
        }
#pragma unroll
        for (int it = 0; it < 8; it++) {
            int f = tid + it * 256;
            int c = f >> 5, dc = f & 31;
            *(float4*)&sV[c * 128 + dc * 4] = *(const float4*)&V[(size_t)(k0 + c) * DDIM + dc * 4];
        }
        __syncthreads();

        float sc[8][4];
#pragma unroll
        for (int i = 0; i < 8; i++)
#pragma unroll
            for (int j = 0; j < 4; j++) sc[i][j] = 0.f;
#pragma unroll 8
        for (int d = 0; d < 128; d++) {
            float qf[8], kf[4];
            *(float4*)&qf[0] = *(float4*)&sQt[d * 128 + ty * 8];
            *(float4*)&qf[4] = *(float4*)&sQt[d * 128 + ty * 8 + 4];
            *(float4*)&kf[0] = *(float4*)&sKt[d * 64 + tx * 4];
#pragma unroll
            for (int i = 0; i < 8; i++)
#pragma unroll
                for (int j = 0; j < 4; j++)
                    sc[i][j] = fmaf(qf[i], kf[j], sc[i][j]);
        }
#pragma unroll
        for (int i = 0; i < 8; i++)
#pragma unroll
            for (int j = 0; j < 4; j++) sc[i][j] *= scale;
        if (k0 + 63 > q0) {
#pragma unroll
            for (int i = 0; i < 8; i++)
#pragma unroll
                for (int j = 0; j < 4; j++)
                    if (k0 + tx * 4 + j > q0 + ty * 8 + i) sc[i][j] = -1e30f;
        }
#pragma unroll
        for (int i = 0; i < 8; i++) {
            float mx = fmaxf(fmaxf(sc[i][0], sc[i][1]), fmaxf(sc[i][2], sc[i][3]));
#pragma unroll
            for (int o = 1; o < 16; o <<= 1) mx = fmaxf(mx, __shfl_xor_sync(0xffffffffu, mx, o));
            float mn = fmaxf(mrow[i], mx);
            float alpha = __expf(mrow[i] - mn);
            mrow[i] = mn;
            float rs = 0.f;
#pragma unroll
            for (int j = 0; j < 4; j++) { float p = __expf(sc[i][j] - mn); sc[i][j] = p; rs += p; }
#pragma unroll
            for (int o = 1; o < 16; o <<= 1) rs += __shfl_xor_sync(0xffffffffu, rs, o);
            lrow[i] = lrow[i] * alpha + rs;
#pragma unroll
            for (int j = 0; j < 8; j++) accO[i][j] *= alpha;
        }
#pragma unroll
        for (int i = 0; i < 8; i++)
#pragma unroll
            for (int j = 0; j < 4; j++)
                sPt[(tx * 4 + j) * 128 + ty * 8 + i] = sc[i][j];
        __syncthreads();
#pragma unroll 4
        for (int c = 0; c < 64; c++) {
            float pf[8], vf[8];
            *(float4*)&pf[0] = *(float4*)&sPt[c * 128 + ty * 8];
            *(float4*)&pf[4] = *(float4*)&sPt[c * 128 + ty * 8 + 4];
            *(float4*)&vf[0] = *(float4*)&sV[c * 128 + tx * 8];
            *(float4*)&vf[4] = *(float4*)&sV[c * 128 + tx * 8 + 4];
#pragma unroll
            for (int i = 0; i < 8; i++)
#pragma unroll
                for (int j = 0; j < 8; j++)
                    accO[i][j] = fmaf(pf[i], vf[j], accO[i][j]);
        }
    }

    // ---- epilogue: normalize, write token-order [B][S][NH*D] ----
#pragma unroll
    for (int i = 0; i < 8; i++) {
        float inv = 1.f / lrow[i];
        int srow = q0 + ty * 8 + i;
        float* dst = &g_ao[(size_t)(b * SS + srow) * HHID + h * DDIM + tx * 8];
        *(float4*)&dst[0] = make_float4(accO[i][0] * inv, accO[i][1] * inv, accO[i][2] * inv, accO[i][3] * inv);
        *(float4*)&dst[4] = make_float4(accO[i][4] * inv, accO[i][5] * inv, accO[i][6] * inv, accO[i][7] * inv);
    }
}

// ===================== kernel: O projection (fp32 SIMT, sorted experts, prefetch k32) =====================
// grid (33, 16). block 256.
__global__ __launch_bounds__(256) void oproj_kernel(
    const float* __restrict__ Wo, float* __restrict__ out)
{
    const int rt = blockIdx.x, ct = blockIdx.y;
    const int tiles0 = (int)g_tiles0_dev;
    const int e = (rt < tiles0) ? 0 : 1;
    const int m0 = rt * 128, n0 = ct * 128;
    const float* W = Wo + (size_t)e * 2048 * 2048;

    __shared__ float As[32][132];
    __shared__ float Bs[32][128];

    const int tid = threadIdx.x;
    const int tx = tid & 15, ty = tid >> 4;
    const int arow = tid >> 2, ag = tid & 3;
    const int asrc0 = g_src[m0 + arow];
    const int asrc1 = g_src[m0 + arow + 64];

    float acc[8][8];
#pragma unroll
    for (int i = 0; i < 8; i++)
#pragma unroll
        for (int j = 0; j < 8; j++) acc[i][j] = 0.f;

    GemmRegs R;
    gemm_load_regs(R, g_ao, asrc0, asrc1, ag, W, 2048, n0, 0, tid);

    for (int k0 = 0; k0 < 2048; k0 += 32) {
        gemm_store_regs(R, As, Bs, arow, ag, tid);
        __syncthreads();
        if (k0 + 32 < 2048)
            gemm_load_regs(R, g_ao, asrc0, asrc1, ag, W, 2048, n0, k0 + 32, tid);
        gemm_compute(As, Bs, tx, ty, acc);
        __syncthreads();
    }

#pragma unroll
    for (int i = 0; i < 8; i++) {
        const int src = g_src[m0 + ty * 8 + i];
        if (src >= 0) {
            float* dst = &out[(size_t)src * 2048 + n0 + tx * 8];
            *(float4*)&dst[0] = make_float4(acc[i][0], acc[i][1], acc[i][2], acc[i][3]);
            *(float4*)&dst[4] = make_float4(acc[i][4], acc[i][5], acc[i][6], acc[i][7]);
        }
    }
}

// =====================================================================
extern "C" void kernel_launch(void* const* d_in, const int* in_sizes, int n_in,
                              void* d_out, int out_size)
{
    const float* hs   = (const float*)d_in[0];
    const int*   tt   = (const int*)  d_in[1];
    const float* cosp = (const float*)d_in[2];
    const float* sinp = (const float*)d_in[3];
    const float* Wq   = (const float*)d_in[4];
    const float* bq   = (const float*)d_in[5];
    const float* Wk   = (const float*)d_in[6];
    const float* bk   = (const float*)d_in[7];
    const float* Wv   = (const float*)d_in[8];
    const float* bv   = (const float*)d_in[9];
    const float* Wo   = (const float*)d_in[10];
    float* out = (float*)d_out;

    cudaFuncSetAttribute(attn_kernel, cudaFuncAttributeMaxDynamicSharedMemorySize, 163840);

    scan_kernel<<<1, 1024>>>(tt);
    qkv_kernel<<<dim3(33, 24), 256>>>(hs, Wq, bq, Wk, bk, Wv, bv, cosp, sinp);
    attn_kernel<<<dim3(16, 32), 256, 163840>>>();
    oproj_kernel<<<dim3(33, 16), 256>>>(Wo, out);
}

// round 13
// speedup vs baseline: 1.5659x; 1.2001x over previous
#include <cuda_runtime.h>
#include <cstdint>
#include <math.h>

#define BB   2
#define SS   2048
#define HHID 2048
#define NHQ  16
#define NKVH 4
#define DDIM 128
#define TTOK (BB*SS)     // 4096
#define PAD_ROWS 4224    // 33 tiles of 128

// ---------------- scratch (~58MB, proven-safe) ----------------
__device__ __align__(16) int g_src[PAD_ROWS];   // sorted row -> src token (-1 = pad)
__device__ unsigned g_tiles0_dev;
__device__ __align__(16) float g_q [(size_t)BB*NHQ *SS*DDIM];   // [B][NH][S][D]  (post-RoPE)
__device__ __align__(16) float g_k [(size_t)BB*NKVH*SS*DDIM];   // [B][NKV][S][D] (post-RoPE)
__device__ __align__(16) float g_v [(size_t)BB*NKVH*SS*DDIM];
__device__ __align__(16) float g_ao[(size_t)TTOK*HHID];         // [B][S][NH*D] token order

// ===================== kernel: expert scan / permutation (proven) =====================
__global__ __launch_bounds__(1024) void scan_kernel(const int* __restrict__ tt)
{
    __shared__ int wtot[32];
    int tid = threadIdx.x, lane = tid & 31, wid = tid >> 5;
    for (int j = tid; j < PAD_ROWS; j += 1024) g_src[j] = -1;
    __syncthreads();

    int t0 = tid * 4;
    int cs[4];
#pragma unroll
    for (int i = 0; i < 4; i++) cs[i] = tt[t0 + i];
    int loc = cs[0] + cs[1] + cs[2] + cs[3];
    int inc = loc;
#pragma unroll
    for (int o = 1; o < 32; o <<= 1) { int v = __shfl_up_sync(0xffffffffu, inc, o); if (lane >= o) inc += v; }
    if (lane == 31) wtot[wid] = inc;
    __syncthreads();
    if (wid == 0) {
        int v = wtot[lane];
#pragma unroll
        for (int o = 1; o < 32; o <<= 1) { int u = __shfl_up_sync(0xffffffffu, v, o); if (lane >= o) v += u; }
        wtot[lane] = v;
    }
    __syncthreads();
    int total1 = wtot[31];
    int base1  = (wid > 0 ? wtot[wid - 1] : 0) + (inc - loc);
    int n0 = TTOK - total1;
    int tiles0 = (n0 + 127) >> 7;
    if (tid == 0) g_tiles0_dev = (unsigned)tiles0;
    int off1 = tiles0 * 128;
    int run1 = base1;
#pragma unroll
    for (int i = 0; i < 4; i++) {
        int idx = t0 + i;
        int dst = cs[i] ? (off1 + run1) : (idx - run1);
        g_src[dst] = idx;
        run1 += cs[i];
    }
}

// ===================== GEMM pieces (k-tile 32, DIRECT loads — no prefetch regs) =====================
__device__ __forceinline__ void gemm_load_tile(
    float (*As)[132], float (*Bs)[128],
    const float* __restrict__ A, int asrc0, int asrc1, int arow, int ag,
    const float* __restrict__ W, int nstr, int n0, int k0, int tid)
{
    const float4 z = make_float4(0.f, 0.f, 0.f, 0.f);
#pragma unroll
    for (int h = 0; h < 2; h++) {
        int g = ag + h * 4;
        float4 v0 = (asrc0 >= 0) ? *(const float4*)&A[(size_t)asrc0 * 2048 + k0 + g * 4] : z;
        float4 v1 = (asrc1 >= 0) ? *(const float4*)&A[(size_t)asrc1 * 2048 + k0 + g * 4] : z;
        As[g * 4 + 0][arow]      = v0.x; As[g * 4 + 1][arow]      = v0.y;
        As[g * 4 + 2][arow]      = v0.z; As[g * 4 + 3][arow]      = v0.w;
        As[g * 4 + 0][arow + 64] = v1.x; As[g * 4 + 1][arow + 64] = v1.y;
        As[g * 4 + 2][arow + 64] = v1.z; As[g * 4 + 3][arow + 64] = v1.w;
    }
#pragma unroll
    for (int it = 0; it < 4; it++) {
        int f = tid + it * 256;
        int kr = f >> 5, nc = f & 31;
        *(float4*)&Bs[kr][nc * 4] = *(const float4*)&W[(size_t)(k0 + kr) * nstr + n0 + nc * 4];
    }
}

__device__ __forceinline__ void gemm_compute(
    const float (*As)[132], const float (*Bs)[128], int tx, int ty, float acc[8][8])
{
#pragma unroll 8
    for (int kk = 0; kk < 32; kk++) {
        float a[8], b[8];
        *(float4*)&a[0] = *(float4*)&As[kk][ty * 8];
        *(float4*)&a[4] = *(float4*)&As[kk][ty * 8 + 4];
        *(float4*)&b[0] = *(float4*)&Bs[kk][tx * 8];
        *(float4*)&b[4] = *(float4*)&Bs[kk][tx * 8 + 4];
#pragma unroll
        for (int i = 0; i < 8; i++)
#pragma unroll
            for (int j = 0; j < 8; j++)
                acc[i][j] = fmaf(a[i], b[j], acc[i][j]);
    }
}

// ===================== kernel: QKV projection + bias + RoPE =====================
// grid (33, 24). block 256.
__global__ __launch_bounds__(256, 2) void qkv_kernel(
    const float* __restrict__ hs,
    const float* __restrict__ Wq, const float* __restrict__ bq,
    const float* __restrict__ Wk, const float* __restrict__ bk,
    const float* __restrict__ Wv, const float* __restrict__ bv,
    const float* __restrict__ cosp, const float* __restrict__ sinp)
{
    const int rt = blockIdx.x, ct = blockIdx.y;
    const int tiles0 = (int)g_tiles0_dev;
    const int e = (rt < tiles0) ? 0 : 1;
    const int m0 = rt * 128;

    const float* W; const float* bias; int nstr, n0, which, head;
    if (ct < 16)      { W = Wq; bias = bq; nstr = 2048; n0 = ct * 128;        which = 0; head = ct;      }
    else if (ct < 20) { W = Wk; bias = bk; nstr = 512;  n0 = (ct - 16) * 128; which = 1; head = ct - 16; }
    else              { W = Wv; bias = bv; nstr = 512;  n0 = (ct - 20) * 128; which = 2; head = ct - 20; }
    W    += (size_t)e * 2048 * nstr;
    bias += (size_t)e * nstr;

    __shared__ float As[32][132];
    __shared__ float Bs[32][128];

    const int tid = threadIdx.x;
    const int tx = tid & 15, ty = tid >> 4;
    const int arow = tid >> 2, ag = tid & 3;
    const int asrc0 = g_src[m0 + arow];
    const int asrc1 = g_src[m0 + arow + 64];

    float acc[8][8];
#pragma unroll
    for (int i = 0; i < 8; i++)
#pragma unroll
        for (int j = 0; j < 8; j++) acc[i][j] = 0.f;

    for (int k0 = 0; k0 < 2048; k0 += 32) {
        gemm_load_tile(As, Bs, hs, asrc0, asrc1, arow, ag, W, nstr, n0, k0, tid);
        __syncthreads();
        gemm_compute(As, Bs, tx, ty, acc);
        __syncthreads();
    }

    // ---- epilogue: bias + fused RoPE (shfl pair) + scatter ----
    const float* bp = bias + n0;
#pragma unroll
    for (int i = 0; i < 8; i++) {
        const int row = m0 + ty * 8 + i;
        const int src = g_src[row];
        const int sEff = (src >= 0) ? src : 0;
        const int b = sEff >> 11, s = sEff & 2047;

        float v8[8];
#pragma unroll
        for (int j = 0; j < 8; j++) v8[j] = acc[i][j] + __ldg(&bp[tx * 8 + j]);

        if (which < 2) {
            float p8[8];
#pragma unroll
            for (int j = 0; j < 8; j++) p8[j] = __shfl_xor_sync(0xffffffffu, v8[j], 8);
            const size_t cb = ((size_t)(b * 2048 + s)) * 128;
#pragma unroll
            for (int j = 0; j < 8; j++) {
                int col = tx * 8 + j;
                float c  = __ldg(&cosp[cb + col]);
                float sn = __ldg(&sinp[cb + col]);
                v8[j] = (tx < 8) ? (v8[j] * c - p8[j] * sn)
                                 : (v8[j] * c + p8[j] * sn);
            }
        }

        if (src >= 0) {
            float* dst;
            if (which == 0)      dst = &g_q[((size_t)((b * NHQ  + head) * SS + s)) * DDIM + tx * 8];
            else if (which == 1) dst = &g_k[((size_t)((b * NKVH + head) * SS + s)) * DDIM + tx * 8];
            else                 dst = &g_v[((size_t)((b * NKVH + head) * SS + s)) * DDIM + tx * 8];
            *(float4*)&dst[0] = make_float4(v8[0], v8[1], v8[2], v8[3]);
            *(float4*)&dst[4] = make_float4(v8[4], v8[5], v8[6], v8[7]);
        }
    }
}

// ===================== kernel: causal flash attention (fp32 SIMT, K/V register prefetch) =====================
// grid: (16 q-tiles [reversed], B*NH=32). BQ=128, BKV=64. smem 160KB (1 block/SM; regs are free).
__global__ __launch_bounds__(256) void attn_kernel()
{
    extern __shared__ float sm[];
    float* sQt = sm;               // [128 d][128 r]
    float* sKt = sm + 16384;       // [128 d][64 c]
    float* sV  = sm + 24576;       // [64 c][128 d]
    float* sPt = sm + 32768;       // [64 c][128 r]

    const int bh = blockIdx.y;
    const int b = bh >> 4, h = bh & 15, hk = h >> 2;
    const int qt = 15 - blockIdx.x;
    const int q0 = qt * 128;
    const float* Q = g_q + (size_t)(b * NHQ  + h ) * SS * DDIM;
    const float* K = g_k + (size_t)(b * NKVH + hk) * SS * DDIM;
    const float* V = g_v + (size_t)(b * NKVH + hk) * SS * DDIM;

    const int tid = threadIdx.x;
    const int tx = tid & 15, ty = tid >> 4;

#pragma unroll
    for (int it = 0; it < 16; it++) {
        int f = tid + it * 256;
        int r = f >> 5, dc = f & 31;
        float4 v = *(const float4*)&Q[(size_t)(q0 + r) * DDIM + dc * 4];
        sQt[(dc * 4 + 0) * 128 + r] = v.x;
        sQt[(dc * 4 + 1) * 128 + r] = v.y;
        sQt[(dc * 4 + 2) * 128 + r] = v.z;
        sQt[(dc * 4 + 3) * 128 + r] = v.w;
    }

    float accO[8][8];
    float mrow[8], lrow[8];
#pragma unroll
    for (int i = 0; i < 8; i++) {
        mrow[i] = -1e30f; lrow[i] = 0.f;
#pragma unroll
        for (int j = 0; j < 8; j++) accO[i][j] = 0.f;
    }

    const float scale = 0.08838834764831845f;
    const int ktiles = 2 * qt + 2;

    // K/V prefetch registers: this thread's 8 float4 of K and 8 of V per tile
    float4 kreg[8], vreg[8];
    {
        const int k0 = 0;
#pragma unroll
        for (int it = 0; it < 8; it++) {
            int f = tid + it * 256;
            int c = f >> 5, dc = f & 31;
            kreg[it] = *(const float4*)&K[(size_t)(k0 + c) * DDIM + dc * 4];
            vreg[it] = *(const float4*)&V[(size_t)(k0 + c) * DDIM + dc * 4];
        }
    }

    for (int kt = 0; kt < ktiles; kt++) {
        __syncthreads();   // prior PV reads of sV/sPt done; safe to overwrite
        // ---- store prefetched K (transposed) and V ----
#pragma unroll
        for (int it = 0; it < 8; it++) {
            int f = tid + it * 256;
            int c = f >> 5, dc = f & 31;
            sKt[(dc * 4 + 0) * 64 + c] = kreg[it].x;
            sKt[(dc * 4 + 1) * 64 + c] = kreg[it].y;
            sKt[(dc * 4 + 2) * 64 + c] = kreg[it].z;
            sKt[(dc * 4 + 3) * 64 + c] = kreg[it].w;
            *(float4*)&sV[c * 128 + dc * 4] = vreg[it];
        }
        __syncthreads();
        // ---- prefetch next tile while computing this one ----
        if (kt + 1 < ktiles) {
            const int kn = (kt + 1) * 64;
#pragma unroll
            for (int it = 0; it < 8; it++) {
                int f = tid + it * 256;
                int c = f >> 5, dc = f & 31;
                kreg[it] = *(const float4*)&K[(size_t)(kn + c) * DDIM + dc * 4];
                vreg[it] = *(const float4*)&V[(size_t)(kn + c) * DDIM + dc * 4];
            }
        }

        const int k0 = kt * 64;
        float sc[8][4];
#pragma unroll
        for (int i = 0; i < 8; i++)
#pragma unroll
            for (int j = 0; j < 4; j++) sc[i][j] = 0.f;
#pragma unroll 8
        for (int d = 0; d < 128; d++) {
            float qf[8], kf[4];
            *(float4*)&qf[0] = *(float4*)&sQt[d * 128 + ty * 8];
            *(float4*)&qf[4] = *(float4*)&sQt[d * 128 + ty * 8 + 4];
            *(float4*)&kf[0] = *(float4*)&sKt[d * 64 + tx * 4];
#pragma unroll
            for (int i = 0; i < 8; i++)
#pragma unroll
                for (int j = 0; j < 4; j++)
                    sc[i][j] = fmaf(qf[i], kf[j], sc[i][j]);
        }
#pragma unroll
        for (int i = 0; i < 8; i++)
#pragma unroll
            for (int j = 0; j < 4; j++) sc[i][j] *= scale;
        if (k0 + 63 > q0) {
#pragma unroll
            for (int i = 0; i < 8; i++)
#pragma unroll
                for (int j = 0; j < 4; j++)
                    if (k0 + tx * 4 + j > q0 + ty * 8 + i) sc[i][j] = -1e30f;
        }
#pragma unroll
        for (int i = 0; i < 8; i++) {
            float mx = fmaxf(fmaxf(sc[i][0], sc[i][1]), fmaxf(sc[i][2], sc[i][3]));
#pragma unroll
            for (int o = 1; o < 16; o <<= 1) mx = fmaxf(mx, __shfl_xor_sync(0xffffffffu, mx, o));
            float mn = fmaxf(mrow[i], mx);
            float alpha = __expf(mrow[i] - mn);
            mrow[i] = mn;
            float rs = 0.f;
#pragma unroll
            for (int j = 0; j < 4; j++) { float p = __expf(sc[i][j] - mn); sc[i][j] = p; rs += p; }
#pragma unroll
            for (int o = 1; o < 16; o <<= 1) rs += __shfl_xor_sync(0xffffffffu, rs, o);
            lrow[i] = lrow[i] * alpha + rs;
#pragma unroll
            for (int j = 0; j < 8; j++) accO[i][j] *= alpha;
        }
#pragma unroll
        for (int i = 0; i < 8; i++)
#pragma unroll
            for (int j = 0; j < 4; j++)
                sPt[(tx * 4 + j) * 128 + ty * 8 + i] = sc[i][j];
        __syncthreads();
#pragma unroll 4
        for (int c = 0; c < 64; c++) {
            float pf[8], vf[8];
            *(float4*)&pf[0] = *(float4*)&sPt[c * 128 + ty * 8];
            *(float4*)&pf[4] = *(float4*)&sPt[c * 128 + ty * 8 + 4];
            *(float4*)&vf[0] = *(float4*)&sV[c * 128 + tx * 8];
            *(float4*)&vf[4] = *(float4*)&sV[c * 128 + tx * 8 + 4];
#pragma unroll
            for (int i = 0; i < 8; i++)
#pragma unroll
                for (int j = 0; j < 8; j++)
                    accO[i][j] = fmaf(pf[i], vf[j], accO[i][j]);
        }
    }

    // ---- epilogue: normalize, write token-order [B][S][NH*D] ----
#pragma unroll
    for (int i = 0; i < 8; i++) {
        float inv = 1.f / lrow[i];
        int srow = q0 + ty * 8 + i;
        float* dst = &g_ao[(size_t)(b * SS + srow) * HHID + h * DDIM + tx * 8];
        *(float4*)&dst[0] = make_float4(accO[i][0] * inv, accO[i][1] * inv, accO[i][2] * inv, accO[i][3] * inv);
        *(float4*)&dst[4] = make_float4(accO[i][4] * inv, accO[i][5] * inv, accO[i][6] * inv, accO[i][7] * inv);
    }
}

// ===================== kernel: O projection (k-tile 32 direct) =====================
// grid (33, 16). block 256.
__global__ __launch_bounds__(256, 2) void oproj_kernel(
    const float* __restrict__ Wo, float* __restrict__ out)
{
    const int rt = blockIdx.x, ct = blockIdx.y;
    const int tiles0 = (int)g_tiles0_dev;
    const int e = (rt < tiles0) ? 0 : 1;
    const int m0 = rt * 128, n0 = ct * 128;
    const float* W = Wo + (size_t)e * 2048 * 2048;

    __shared__ float As[32][132];
    __shared__ float Bs[32][128];

    const int tid = threadIdx.x;
    const int tx = tid & 15, ty = tid >> 4;
    const int arow = tid >> 2, ag = tid & 3;
    const int asrc0 = g_src[m0 + arow];
    const int asrc1 = g_src[m0 + arow + 64];

    float acc[8][8];
#pragma unroll
    for (int i = 0; i < 8; i++)
#pragma unroll
        for (int j = 0; j < 8; j++) acc[i][j] = 0.f;

    for (int k0 = 0; k0 < 2048; k0 += 32) {
        gemm_load_tile(As, Bs, g_ao, asrc0, asrc1, arow, ag, W, 2048, n0, k0, tid);
        __syncthreads();
        gemm_compute(As, Bs, tx, ty, acc);
        __syncthreads();
    }

#pragma unroll
    for (int i = 0; i < 8; i++) {
        const int src = g_src[m0 + ty * 8 + i];
        if (src >= 0) {
            float* dst = &out[(size_t)src * 2048 + n0 + tx * 8];
            *(float4*)&dst[0] = make_float4(acc[i][0], acc[i][1], acc[i][2], acc[i][3]);
            *(float4*)&dst[4] = make_float4(acc[i][4], acc[i][5], acc[i][6], acc[i][7]);
        }
    }
}

// =====================================================================
extern "C" void kernel_launch(void* const* d_in, const int* in_sizes, int n_in,
                              void* d_out, int out_size)
{
    const float* hs   = (const float*)d_in[0];
    const int*   tt   = (const int*)  d_in[1];
    const float* cosp = (const float*)d_in[2];
    const float* sinp = (const float*)d_in[3];
    const float* Wq   = (const float*)d_in[4];
    const float* bq   = (const float*)d_in[5];
    const float* Wk   = (const float*)d_in[6];
    const float* bk   = (const float*)d_in[7];
    const float* Wv   = (const float*)d_in[8];
    const float* bv   = (const float*)d_in[9];
    const float* Wo   = (const float*)d_in[10];
    float* out = (float*)d_out;

    cudaFuncSetAttribute(attn_kernel, cudaFuncAttributeMaxDynamicSharedMemorySize, 163840);

    scan_kernel<<<1, 1024>>>(tt);
    qkv_kernel<<<dim3(33, 24), 256>>>(hs, Wq, bq, Wk, bk, Wv, bv, cosp, sinp);
    attn_kernel<<<dim3(16, 32), 256, 163840>>>();
    oproj_kernel<<<dim3(33, 16), 256>>>(Wo, out);
}

// round 14
// speedup vs baseline: 1.5903x; 1.0156x over previous
#include <cuda_runtime.h>
#include <cstdint>
#include <math.h>

#define BB   2
#define SS   2048
#define HHID 2048
#define NHQ  16
#define NKVH 4
#define DDIM 128
#define TTOK (BB*SS)     // 4096
#define PAD_ROWS 4224    // 33 tiles of 128

// ---------------- scratch (~58MB, proven-safe) ----------------
__device__ __align__(16) int g_src[PAD_ROWS];   // sorted row -> src token (-1 = pad)
__device__ unsigned g_tiles0_dev;
__device__ __align__(16) float g_q [(size_t)BB*NHQ *SS*DDIM];   // [B][NH][S][D]  (post-RoPE)
__device__ __align__(16) float g_k [(size_t)BB*NKVH*SS*DDIM];   // [B][NKV][S][D] (post-RoPE)
__device__ __align__(16) float g_v [(size_t)BB*NKVH*SS*DDIM];
__device__ __align__(16) float g_ao[(size_t)TTOK*HHID];         // [B][S][NH*D] token order

// ---------------- cp.async helpers ----------------
__device__ __forceinline__ uint32_t smem_u32(const void* p) {
    uint32_t a;
    asm("{ .reg .u64 t; cvta.to.shared.u64 t, %1; cvt.u32.u64 %0, t; }" : "=r"(a) : "l"(p));
    return a;
}
__device__ __forceinline__ void cp16(uint32_t d, const void* s) {
    uint64_t gs;
    asm("cvta.to.global.u64 %0, %1;" : "=l"(gs) : "l"(s));
    asm volatile("cp.async.cg.shared.global [%0], [%1], 16;" :: "r"(d), "l"(gs) : "memory");
}
#define CP_COMMIT() asm volatile("cp.async.commit_group;" ::: "memory")
#define CP_WAIT1()  asm volatile("cp.async.wait_group 1;" ::: "memory")
#define CP_WAIT0()  asm volatile("cp.async.wait_group 0;" ::: "memory")

// GEMM dynamic smem layout: As [32][132] fp32, then Bs[2][32][128] fp32
#define OFF_BS  16896
#define BS_STG  16384
#define SMEM_G  (OFF_BS + 2*BS_STG)   // 49664

// ===================== kernel: expert scan / permutation (proven) =====================
__global__ __launch_bounds__(1024) void scan_kernel(const int* __restrict__ tt)
{
    __shared__ int wtot[32];
    int tid = threadIdx.x, lane = tid & 31, wid = tid >> 5;
    for (int j = tid; j < PAD_ROWS; j += 1024) g_src[j] = -1;
    __syncthreads();

    int t0 = tid * 4;
    int cs[4];
#pragma unroll
    for (int i = 0; i < 4; i++) cs[i] = tt[t0 + i];
    int loc = cs[0] + cs[1] + cs[2] + cs[3];
    int inc = loc;
#pragma unroll
    for (int o = 1; o < 32; o <<= 1) { int v = __shfl_up_sync(0xffffffffu, inc, o); if (lane >= o) inc += v; }
    if (lane == 31) wtot[wid] = inc;
    __syncthreads();
    if (wid == 0) {
        int v = wtot[lane];
#pragma unroll
        for (int o = 1; o < 32; o <<= 1) { int u = __shfl_up_sync(0xffffffffu, v, o); if (lane >= o) v += u; }
        wtot[lane] = v;
    }
    __syncthreads();
    int total1 = wtot[31];
    int base1  = (wid > 0 ? wtot[wid - 1] : 0) + (inc - loc);
    int n0 = TTOK - total1;
    int tiles0 = (n0 + 127) >> 7;
    if (tid == 0) g_tiles0_dev = (unsigned)tiles0;
    int off1 = tiles0 * 128;
    int run1 = base1;
#pragma unroll
    for (int i = 0; i < 4; i++) {
        int idx = t0 + i;
        int dst = cs[i] ? (off1 + run1) : (idx - run1);
        g_src[dst] = idx;
        run1 += cs[i];
    }
}

// ===================== GEMM pieces (k-tile 32; A direct, B cp.async double-buffered) =====================
__device__ __forceinline__ void load_A_tile(
    float (*As)[132],
    const float* __restrict__ A, int asrc0, int asrc1, int arow, int ag, int k0)
{
    const float4 z = make_float4(0.f, 0.f, 0.f, 0.f);
#pragma unroll
    for (int h = 0; h < 2; h++) {
        int g = ag + h * 4;
        float4 v0 = (asrc0 >= 0) ? *(const float4*)&A[(size_t)asrc0 * 2048 + k0 + g * 4] : z;
        float4 v1 = (asrc1 >= 0) ? *(const float4*)&A[(size_t)asrc1 * 2048 + k0 + g * 4] : z;
        As[g * 4 + 0][arow]      = v0.x; As[g * 4 + 1][arow]      = v0.y;
        As[g * 4 + 2][arow]      = v0.z; As[g * 4 + 3][arow]      = v0.w;
        As[g * 4 + 0][arow + 64] = v1.x; As[g * 4 + 1][arow + 64] = v1.y;
        As[g * 4 + 2][arow + 64] = v1.z; As[g * 4 + 3][arow + 64] = v1.w;
    }
}

__device__ __forceinline__ void issue_B_tile(uint32_t bsAddr,
    const float* __restrict__ W, int nstr, int n0, int k0, int tid)
{
#pragma unroll
    for (int it = 0; it < 4; it++) {
        int f = tid + it * 256;
        int kr = f >> 5, nc = f & 31;
        cp16(bsAddr + (uint32_t)(kr * 128 + nc * 4) * 4,
             &W[(size_t)(k0 + kr) * nstr + n0 + nc * 4]);
    }
    CP_COMMIT();
}

__device__ __forceinline__ void gemm_compute(
    const float (*As)[132], const float (*Bs)[128], int tx, int ty, float acc[8][8])
{
#pragma unroll 8
    for (int kk = 0; kk < 32; kk++) {
        float a[8], b[8];
        *(float4*)&a[0] = *(float4*)&As[kk][ty * 8];
        *(float4*)&a[4] = *(float4*)&As[kk][ty * 8 + 4];
        *(float4*)&b[0] = *(float4*)&Bs[kk][tx * 8];
        *(float4*)&b[4] = *(float4*)&Bs[kk][tx * 8 + 4];
#pragma unroll
        for (int i = 0; i < 8; i++)
#pragma unroll
            for (int j = 0; j < 8; j++)
                acc[i][j] = fmaf(a[i], b[j], acc[i][j]);
    }
}

// shared mainloop: As single-buffer direct, Bs double-buffer cp.async
__device__ __forceinline__ void gemm_mainloop(char* smem,
    const float* __restrict__ A, int asrc0, int asrc1, int arow, int ag,
    const float* __restrict__ W, int nstr, int n0, int tid, int tx, int ty,
    float acc[8][8])
{
    float (*As)[132] = (float(*)[132])smem;
    uint32_t bsBase = smem_u32(smem + OFF_BS);

    issue_B_tile(bsBase, W, nstr, n0, 0, tid);   // stage 0

    for (int s = 0; s < 64; s++) {
        const int k0 = s * 32;
        __syncthreads();                          // compute s-1 done: As free, Bs[(s+1)&1] free
        load_A_tile(As, A, asrc0, asrc1, arow, ag, k0);
        if (s + 1 < 64) {
            issue_B_tile(bsBase + ((s + 1) & 1) * BS_STG, W, nstr, n0, k0 + 32, tid);
            CP_WAIT1();                           // stage s complete
        } else {
            CP_WAIT0();
        }
        __syncthreads();                          // As stored + Bs[s&1] visible
        gemm_compute(As, (const float(*)[128])(smem + OFF_BS + (s & 1) * BS_STG), tx, ty, acc);
    }
}

// ===================== kernel: QKV projection + bias + RoPE =====================
// grid (33, 24). block 256. dyn smem SMEM_G.
__global__ __launch_bounds__(256, 2) void qkv_kernel(
    const float* __restrict__ hs,
    const float* __restrict__ Wq, const float* __restrict__ bq,
    const float* __restrict__ Wk, const float* __restrict__ bk,
    const float* __restrict__ Wv, const float* __restrict__ bv,
    const float* __restrict__ cosp, const float* __restrict__ sinp)
{
    extern __shared__ char smq[];
    const int rt = blockIdx.x, ct = blockIdx.y;
    const int tiles0 = (int)g_tiles0_dev;
    const int e = (rt < tiles0) ? 0 : 1;
    const int m0 = rt * 128;

    const float* W; const float* bias; int nstr, n0, which, head;
    if (ct < 16)      { W = Wq; bias = bq; nstr = 2048; n0 = ct * 128;        which = 0; head = ct;      }
    else if (ct < 20) { W = Wk; bias = bk; nstr = 512;  n0 = (ct - 16) * 128; which = 1; head = ct - 16; }
    else              { W = Wv; bias = bv; nstr = 512;  n0 = (ct - 20) * 128; which = 2; head = ct - 20; }
    W    += (size_t)e * 2048 * nstr;
    bias += (size_t)e * nstr;

    const int tid = threadIdx.x;
    const int tx = tid & 15, ty = tid >> 4;
    const int arow = tid >> 2, ag = tid & 3;
    const int asrc0 = g_src[m0 + arow];
    const int asrc1 = g_src[m0 + arow + 64];

    float acc[8][8];
#pragma unroll
    for (int i = 0; i < 8; i++)
#pragma unroll
        for (int j = 0; j < 8; j++) acc[i][j] = 0.f;

    gemm_mainloop(smq, hs, asrc0, asrc1, arow, ag, W, nstr, n0, tid, tx, ty, acc);

    // ---- epilogue: bias + fused RoPE (shfl pair) + scatter ----
    const float* bp = bias + n0;
#pragma unroll
    for (int i = 0; i < 8; i++) {
        const int row = m0 + ty * 8 + i;
        const int src = g_src[row];
        const int sEff = (src >= 0) ? src : 0;
        const int b = sEff >> 11, s = sEff & 2047;

        float v8[8];
#pragma unroll
        for (int j = 0; j < 8; j++) v8[j] = acc[i][j] + __ldg(&bp[tx * 8 + j]);

        if (which < 2) {
            float p8[8];
#pragma unroll
            for (int j = 0; j < 8; j++) p8[j] = __shfl_xor_sync(0xffffffffu, v8[j], 8);
            const size_t cb = ((size_t)(b * 2048 + s)) * 128;
#pragma unroll
            for (int j = 0; j < 8; j++) {
                int col = tx * 8 + j;
                float c  = __ldg(&cosp[cb + col]);
                float sn = __ldg(&sinp[cb + col]);
                v8[j] = (tx < 8) ? (v8[j] * c - p8[j] * sn)
                                 : (v8[j] * c + p8[j] * sn);
            }
        }

        if (src >= 0) {
            float* dst;
            if (which == 0)      dst = &g_q[((size_t)((b * NHQ  + head) * SS + s)) * DDIM + tx * 8];
            else if (which == 1) dst = &g_k[((size_t)((b * NKVH + head) * SS + s)) * DDIM + tx * 8];
            else                 dst = &g_v[((size_t)((b * NKVH + head) * SS + s)) * DDIM + tx * 8];
            *(float4*)&dst[0] = make_float4(v8[0], v8[1], v8[2], v8[3]);
            *(float4*)&dst[4] = make_float4(v8[4], v8[5], v8[6], v8[7]);
        }
    }
}

// ===================== kernel: causal flash attention (fp32 SIMT, K/V register prefetch) — R13 proven =====================
__global__ __launch_bounds__(256) void attn_kernel()
{
    extern __shared__ float sm[];
    float* sQt = sm;               // [128 d][128 r]
    float* sKt = sm + 16384;       // [128 d][64 c]
    float* sV  = sm + 24576;       // [64 c][128 d]
    float* sPt = sm + 32768;       // [64 c][128 r]

    const int bh = blockIdx.y;
    const int b = bh >> 4, h = bh & 15, hk = h >> 2;
    const int qt = 15 - blockIdx.x;
    const int q0 = qt * 128;
    const float* Q = g_q + (size_t)(b * NHQ  + h ) * SS * DDIM;
    const float* K = g_k + (size_t)(b * NKVH + hk) * SS * DDIM;
    const float* V = g_v + (size_t)(b * NKVH + hk) * SS * DDIM;

    const int tid = threadIdx.x;
    const int tx = tid & 15, ty = tid >> 4;

#pragma unroll
    for (int it = 0; it < 16; it++) {
        int f = tid + it * 256;
        int r = f >> 5, dc = f & 31;
        float4 v = *(const float4*)&Q[(size_t)(q0 + r) * DDIM + dc * 4];
        sQt[(dc * 4 + 0) * 128 + r] = v.x;
        sQt[(dc * 4 + 1) * 128 + r] = v.y;
        sQt[(dc * 4 + 2) * 128 + r] = v.z;
        sQt[(dc * 4 + 3) * 128 + r] = v.w;
    }

    float accO[8][8];
    float mrow[8], lrow[8];
#pragma unroll
    for (int i = 0; i < 8; i++) {
        mrow[i] = -1e30f; lrow[i] = 0.f;
#pragma unroll
        for (int j = 0; j < 8; j++) accO[i][j] = 0.f;
    }

    const float scale = 0.08838834764831845f;
    const int ktiles = 2 * qt + 2;

    float4 kreg[8], vreg[8];
    {
#pragma unroll
        for (int it = 0; it < 8; it++) {
            int f = tid + it * 256;
            int c = f >> 5, dc = f & 31;
            kreg[it] = *(const float4*)&K[(size_t)c * DDIM + dc * 4];
            vreg[it] = *(const float4*)&V[(size_t)c * DDIM + dc * 4];
        }
    }

    for (int kt = 0; kt < ktiles; kt++) {
        __syncthreads();
#pragma unroll
        for (int it = 0; it < 8; it++) {
            int f = tid + it * 256;
            int c = f >> 5, dc = f & 31;
            sKt[(dc * 4 + 0) * 64 + c] = kreg[it].x;
            sKt[(dc * 4 + 1) * 64 + c] = kreg[it].y;
            sKt[(dc * 4 + 2) * 64 + c] = kreg[it].z;
            sKt[(dc * 4 + 3) * 64 + c] = kreg[it].w;
            *(float4*)&sV[c * 128 + dc * 4] = vreg[it];
        }
        __syncthreads();
        if (kt + 1 < ktiles) {
            const int kn = (kt + 1) * 64;
#pragma unroll
            for (int it = 0; it < 8; it++) {
                int f = tid + it * 256;
                int c = f >> 5, dc = f & 31;
                kreg[it] = *(const float4*)&K[(size_t)(kn + c) * DDIM + dc * 4];
                vreg[it] = *(const float4*)&V[(size_t)(kn + c) * DDIM + dc * 4];
            }
        }

        const int k0 = kt * 64;
        float sc[8][4];
#pragma unroll
        for (int i = 0; i < 8; i++)
#pragma unroll
            for (int j = 0; j < 4; j++) sc[i][j] = 0.f;
#pragma unroll 8
        for (int d = 0; d < 128; d++) {
            float qf[8], kf[4];
            *(float4*)&qf[0] = *(float4*)&sQt[d * 128 + ty * 8];
            *(float4*)&qf[4] = *(float4*)&sQt[d * 128 + ty * 8 + 4];
            *(float4*)&kf[0] = *(float4*)&sKt[d * 64 + tx * 4];
#pragma unroll
            for (int i = 0; i < 8; i++)
#pragma unroll
                for (int j = 0; j < 4; j++)
                    sc[i][j] = fmaf(qf[i], kf[j], sc[i][j]);
        }
#pragma unroll
        for (int i = 0; i < 8; i++)
#pragma unroll
            for (int j = 0; j < 4; j++) sc[i][j] *= scale;
        if (k0 + 63 > q0) {
#pragma unroll
            for (int i = 0; i < 8; i++)
#pragma unroll
                for (int j = 0; j < 4; j++)
                    if (k0 + tx * 4 + j > q0 + ty * 8 + i) sc[i][j] = -1e30f;
        }
#pragma unroll
        for (int i = 0; i < 8; i++) {
            float mx = fmaxf(fmaxf(sc[i][0], sc[i][1]), fmaxf(sc[i][2], sc[i][3]));
#pragma unroll
            for (int o = 1; o < 16; o <<= 1) mx = fmaxf(mx, __shfl_xor_sync(0xffffffffu, mx, o));
            float mn = fmaxf(mrow[i], mx);
            float alpha = __expf(mrow[i] - mn);
            mrow[i] = mn;
            float rs = 0.f;
#pragma unroll
            for (int j = 0; j < 4; j++) { float p = __expf(sc[i][j] - mn); sc[i][j] = p; rs += p; }
#pragma unroll
            for (int o = 1; o < 16; o <<= 1) rs += __shfl_xor_sync(0xffffffffu, rs, o);
            lrow[i] = lrow[i] * alpha + rs;
#pragma unroll
            for (int j = 0; j < 8; j++) accO[i][j] *= alpha;
        }
#pragma unroll
        for (int i = 0; i < 8; i++)
#pragma unroll
            for (int j = 0; j < 4; j++)
                sPt[(tx * 4 + j) * 128 + ty * 8 + i] = sc[i][j];
        __syncthreads();
#pragma unroll 4
        for (int c = 0; c < 64; c++) {
            float pf[8], vf[8];
            *(float4*)&pf[0] = *(float4*)&sPt[c * 128 + ty * 8];
            *(float4*)&pf[4] = *(float4*)&sPt[c * 128 + ty * 8 + 4];
            *(float4*)&vf[0] = *(float4*)&sV[c * 128 + tx * 8];
            *(float4*)&vf[4] = *(float4*)&sV[c * 128 + tx * 8 + 4];
#pragma unroll
            for (int i = 0; i < 8; i++)
#pragma unroll
                for (int j = 0; j < 8; j++)
                    accO[i][j] = fmaf(pf[i], vf[j], accO[i][j]);
        }
    }

#pragma unroll
    for (int i = 0; i < 8; i++) {
        float inv = 1.f / lrow[i];
        int srow = q0 + ty * 8 + i;
        float* dst = &g_ao[(size_t)(b * SS + srow) * HHID + h * DDIM + tx * 8];
        *(float4*)&dst[0] = make_float4(accO[i][0] * inv, accO[i][1] * inv, accO[i][2] * inv, accO[i][3] * inv);
        *(float4*)&dst[4] = make_float4(accO[i][4] * inv, accO[i][5] * inv, accO[i][6] * inv, accO[i][7] * inv);
    }
}

// ===================== kernel: O projection (cp.async B double-buffer) =====================
// grid (33, 16). block 256. dyn smem SMEM_G.
__global__ __launch_bounds__(256, 2) void oproj_kernel(
    const float* __restrict__ Wo, float* __restrict__ out)
{
    extern __shared__ char smo[];
    const int rt = blockIdx.x, ct = blockIdx.y;
    const int tiles0 = (int)g_tiles0_dev;
    const int e = (rt < tiles0) ? 0 : 1;
    const int m0 = rt * 128, n0 = ct * 128;
    const float* W = Wo + (size_t)e * 2048 * 2048;

    const int tid = threadIdx.x;
    const int tx = tid & 15, ty = tid >> 4;
    const int arow = tid >> 2, ag = tid & 3;
    const int asrc0 = g_src[m0 + arow];
    const int asrc1 = g_src[m0 + arow + 64];

    float acc[8][8];
#pragma unroll
    for (int i = 0; i < 8; i++)
#pragma unroll
        for (int j = 0; j < 8; j++) acc[i][j] = 0.f;

    gemm_mainloop(smo, g_ao, asrc0, asrc1, arow, ag, W, 2048, n0, tid, tx, ty, acc);

#pragma unroll
    for (int i = 0; i < 8; i++) {
        const int src = g_src[m0 + ty * 8 + i];
        if (src >= 0) {
            float* dst = &out[(size_t)src * 2048 + n0 + tx * 8];
            *(float4*)&dst[0] = make_float4(acc[i][0], acc[i][1], acc[i][2], acc[i][3]);
            *(float4*)&dst[4] = make_float4(acc[i][4], acc[i][5], acc[i][6], acc[i][7]);
        }
    }
}

// =====================================================================
extern "C" void kernel_launch(void* const* d_in, const int* in_sizes, int n_in,
                              void* d_out, int out_size)
{
    const float* hs   = (const float*)d_in[0];
    const int*   tt   = (const int*)  d_in[1];
    const float* cosp = (const float*)d_in[2];
    const float* sinp = (const float*)d_in[3];
    const float* Wq   = (const float*)d_in[4];
    const float* bq   = (const float*)d_in[5];
    const float* Wk   = (const float*)d_in[6];
    const float* bk   = (const float*)d_in[7];
    const float* Wv   = (const float*)d_in[8];
    const float* bv   = (const float*)d_in[9];
    const float* Wo   = (const float*)d_in[10];
    float* out = (float*)d_out;

    cudaFuncSetAttribute(attn_kernel,  cudaFuncAttributeMaxDynamicSharedMemorySize, 163840);
    cudaFuncSetAttribute(qkv_kernel,   cudaFuncAttributeMaxDynamicSharedMemorySize, SMEM_G);
    cudaFuncSetAttribute(oproj_kernel, cudaFuncAttributeMaxDynamicSharedMemorySize, SMEM_G);

    scan_kernel<<<1, 1024>>>(tt);
    qkv_kernel<<<dim3(33, 24), 256, SMEM_G>>>(hs, Wq, bq, Wk, bk, Wv, bv, cosp, sinp);
    attn_kernel<<<dim3(16, 32), 256, 163840>>>();
    oproj_kernel<<<dim3(33, 16), 256, SMEM_G>>>(Wo, out);
}